// round 16
// baseline (speedup 1.0000x reference)
#include <cuda_runtime.h>

// Shapes (fixed by the problem): T=1024, B=4096, D=16, NQ=H=4.
#define T_LEN 1024
#define B_SZ  4096

// 16 threads per batch element: lane sub = q*4 + w  (q = gate f/i/g/o, w = wire).
// Each thread computes angle(q,w) = dot(comb, W_q[w,:]) + b_q[w] + rx_q[w],
// c = cos(angle), then the qlayer output is the inclusive prefix product of c
// over w (CNOT chain + PauliZ collapses to  Π_{j<=w} cos(theta_j)).
// Gates: f,i,o -> sigmoid ; g -> tanh.  Cell: cx = f*cx + i*g ; hx = o*tanh(cx).

__global__ __launch_bounds__(64, 16)
void qlstm_kernel(const float* __restrict__ x,
                  const float* __restrict__ W_f, const float* __restrict__ b_f,
                  const float* __restrict__ W_i, const float* __restrict__ b_i,
                  const float* __restrict__ W_g, const float* __restrict__ b_g,
                  const float* __restrict__ W_o, const float* __restrict__ b_o,
                  const float* __restrict__ rx_f, const float* __restrict__ rx_i,
                  const float* __restrict__ rx_g, const float* __restrict__ rx_o,
                  float* __restrict__ out)
{
    const int lane = threadIdx.x & 31;
    const int warp = threadIdx.x >> 5;       // 0..1
    const int grp  = lane >> 4;              // element within warp: 0..1
    const int sub  = lane & 15;              // 0..15
    const int q    = sub >> 2;               // gate: 0=f 1=i 2=g 3=o
    const int w    = sub & 3;                // wire
    const int elem = warp * 2 + grp;         // element within block: 0..3
    const int b    = blockIdx.x * 4 + elem;  // batch element: 0..4095

    // Per-thread weight row (gate q, wire w): 16 x-weights, 4 h-weights, bias.
    const float* Wq  = (q == 0) ? W_f : (q == 1) ? W_i : (q == 2) ? W_g : W_o;
    const float* bq  = (q == 0) ? b_f : (q == 1) ? b_i : (q == 2) ? b_g : b_o;
    const float* rxq = (q == 0) ? rx_f : (q == 1) ? rx_i : (q == 2) ? rx_g : rx_o;

    float wx[16];
#pragma unroll
    for (int d = 0; d < 16; d++) wx[d] = Wq[w * 20 + d];
    const float wh0 = Wq[w * 20 + 16];
    const float wh1 = Wq[w * 20 + 17];
    const float wh2 = Wq[w * 20 + 18];
    const float wh3 = Wq[w * 20 + 19];
    const float bias = bq[w] + rxq[w];

    // Unified nonlinearity: val = na * sigmoid(nb * p) + nc
    //   sigmoid: (1,1,0)   tanh: (2,2,-1)   (tanh(x) = 2*sigmoid(2x) - 1)
    const float na = (q == 2) ? 2.0f : 1.0f;
    const float nb = na;
    const float nc = (q == 2) ? -1.0f : 0.0f;

    // Per-warp-private staging buffers (only __syncwarp needed).
    __shared__ __align__(16) float xbuf[4][16];  // x broadcast
    __shared__ __align__(16) float gbuf[4][16];  // gate vals, transposed [w][q]
    __shared__ __align__(16) float hbuf[4][4];   // hx broadcast

    float  cx = 0.0f;                 // cx[w], replicated across the 4 q-lanes
    float4 hx = make_float4(0.f, 0.f, 0.f, 0.f);
    float  hv = 0.0f;

    const float* xp = x + (size_t)b * 16 + sub;          // [T,B,16]
    float*       op = out + (size_t)b * 4 + w;           // stacked [T,B,4]
    const size_t xstride = (size_t)B_SZ * 16;
    const size_t ostride = (size_t)B_SZ * 4;

    for (int t = 0; t < T_LEN; t++) {
        // ---- stage x[t,b,:] (coalesced: warp reads 128B contiguous) ----
        xbuf[elem][sub] = __ldg(xp);
        xp += xstride;
        __syncwarp();
        const float4 X0 = *(const float4*)&xbuf[elem][0];
        const float4 X1 = *(const float4*)&xbuf[elem][4];
        const float4 X2 = *(const float4*)&xbuf[elem][8];
        const float4 X3 = *(const float4*)&xbuf[elem][12];

        // ---- angle = W_x . x + W_h . hx + bias   (4 independent FMA chains) ----
        float a0 = fmaf(wx[0],  X0.x, bias);
        float a1 = wx[1] * X0.y;
        float a2 = wx[2] * X0.z;
        float a3 = wx[3] * X0.w;
        a0 = fmaf(wx[4],  X1.x, a0);
        a1 = fmaf(wx[5],  X1.y, a1);
        a2 = fmaf(wx[6],  X1.z, a2);
        a3 = fmaf(wx[7],  X1.w, a3);
        a0 = fmaf(wx[8],  X2.x, a0);
        a1 = fmaf(wx[9],  X2.y, a1);
        a2 = fmaf(wx[10], X2.z, a2);
        a3 = fmaf(wx[11], X2.w, a3);
        a0 = fmaf(wx[12], X3.x, a0);
        a1 = fmaf(wx[13], X3.y, a1);
        a2 = fmaf(wx[14], X3.z, a2);
        a3 = fmaf(wx[15], X3.w, a3);
        a0 = fmaf(wh0, hx.x, a0);
        a1 = fmaf(wh1, hx.y, a1);
        a2 = fmaf(wh2, hx.z, a2);
        a3 = fmaf(wh3, hx.w, a3);
        const float acc = (a0 + a1) + (a2 + a3);

        // ---- cos + inclusive prefix product over wires (width-4 segments) ----
        float c = __cosf(acc);
        const float u1 = __shfl_up_sync(0xffffffffu, c, 1, 4);
        c = (w >= 1) ? c * u1 : c;
        const float u2 = __shfl_up_sync(0xffffffffu, c, 2, 4);
        c = (w >= 2) ? c * u2 : c;

        // ---- nonlinearity (branch-free sigmoid/tanh) ----
        const float s   = __fdividef(1.0f, 1.0f + __expf(-nb * c));
        const float val = fmaf(na, s, nc);

        // ---- gather f,i,g,o for this wire via transposed SMEM store ----
        gbuf[elem][w * 4 + q] = val;
        __syncwarp();
        const float4 G = *(const float4*)&gbuf[elem][w * 4];  // (f,i,g,o)[w]

        // ---- cell update (identical on all 4 q-lanes of this wire) ----
        cx = fmaf(G.x, cx, G.y * G.z);
        const float e2 = __expf(2.0f * cx);
        const float th = 1.0f - __fdividef(2.0f, e2 + 1.0f);  // tanh(cx)
        hv = G.w * th;

        if (q == 0) hbuf[elem][w] = hv;
        __syncwarp();
        hx = *(const float4*)&hbuf[elem][0];

        if (q == 0) *op = hv;   // stacked output hx[t]
        op += ostride;
    }

    // final hx, cx appended after the stacked output
    if (q == 0) {
        const size_t base = (size_t)T_LEN * B_SZ * 4;
        out[base + (size_t)b * 4 + w] = hv;
        out[base + (size_t)B_SZ * 4 + (size_t)b * 4 + w] = cx;
    }
}

extern "C" void kernel_launch(void* const* d_in, const int* in_sizes, int n_in,
                              void* d_out, int out_size)
{
    (void)in_sizes; (void)n_in; (void)out_size;
    const float* x    = (const float*)d_in[0];
    const float* W_f  = (const float*)d_in[1];
    const float* b_f  = (const float*)d_in[2];
    const float* W_i  = (const float*)d_in[3];
    const float* b_i  = (const float*)d_in[4];
    const float* W_g  = (const float*)d_in[5];
    const float* b_g  = (const float*)d_in[6];
    const float* W_o  = (const float*)d_in[7];
    const float* b_o  = (const float*)d_in[8];
    const float* rx_f = (const float*)d_in[9];
    const float* rx_i = (const float*)d_in[10];
    const float* rx_g = (const float*)d_in[11];
    const float* rx_o = (const float*)d_in[12];
    float* out = (float*)d_out;

    // 4096 batch elements, 4 per 64-thread block -> 1024 blocks (~6.9 CTAs/SM).
    qlstm_kernel<<<B_SZ / 4, 64>>>(x, W_f, b_f, W_i, b_i, W_g, b_g, W_o, b_o,
                                   rx_f, rx_i, rx_g, rx_o, out);
}